// round 8
// baseline (speedup 1.0000x reference)
#include <cuda_runtime.h>
#include <math.h>

#define N_NODES 50000
#define N_EDGES 800000
#define NUM_RELS 16
#define H_DIM 128
#define LIN_DIM 512

#define CAP1 256
#define CAP2 2048
#define CAPE1 512
#define CAPE2 4096
#define ESTG  2048          // smem staging cap for E2 list

#define BM_WORDS ((N_NODES + 31) / 32)

#define NB 444              // 3 blocks/SM on 148 SMs
#define NT 512
#define NQ (N_EDGES / 4)    // 200000 int4 quads
#define QPB ((NQ + NB - 1) / NB)   // 451 quads per block (contiguous slice)

// -------- scratch (device globals, zero-init is the valid empty state) --------
// slot encoding: 0 = absent, otherwise slot+1
__device__ int          g_slot1[N_NODES];
__device__ int          g_slot2[N_NODES];
__device__ unsigned int g_bm1[BM_WORDS + 1];
__device__ unsigned int g_bm2[BM_WORDS + 1];
__device__ int   g_n1, g_n2, g_ne1, g_ne2;
__device__ int   g_s1_nodes[CAP1];
__device__ int   g_s2_nodes[CAP2];
__device__ int   g_e1_src[CAPE1];
__device__ int   g_e2_src[CAPE2];
__device__ int   g_e2_dslot[CAPE2];          // 0-based slot1 of dst
__device__ float g_S[CAP2 * NUM_RELS];       // per-(S2-slot, rel) scalar sums
__device__ float g_msg1[CAP2 * H_DIM];
__device__ float g_root[H_DIM];

// persistent-generation grid barrier (state persists across graph replays)
__device__ unsigned g_bar_cnt;
__device__ unsigned g_bar_gen;

// ---- release/acquire primitives ----
__device__ __forceinline__ unsigned atom_add_release_gpu(unsigned* p, unsigned v) {
    unsigned old;
    asm volatile("atom.add.release.gpu.u32 %0, [%1], %2;"
                 : "=r"(old) : "l"(p), "r"(v) : "memory");
    return old;
}
__device__ __forceinline__ unsigned ld_acquire_gpu(unsigned* p) {
    unsigned v;
    asm volatile("ld.acquire.gpu.u32 %0, [%1];" : "=r"(v) : "l"(p) : "memory");
    return v;
}
__device__ __forceinline__ void st_release_gpu(unsigned* p, unsigned v) {
    asm volatile("st.release.gpu.u32 [%0], %1;" :: "l"(p), "r"(v) : "memory");
}

#define GRID_SYNC()                                                          \
    do {                                                                     \
        __syncthreads();                                                     \
        if (threadIdx.x == 0) {                                              \
            if (atom_add_release_gpu(&g_bar_cnt, 1u) == (unsigned)(NB - 1)) {\
                *(volatile unsigned*)&g_bar_cnt = 0u;                        \
                st_release_gpu(&g_bar_gen, my_gen + 1u);                     \
            } else {                                                         \
                int spin = 0;                                                \
                while (ld_acquire_gpu(&g_bar_gen) == my_gen)                 \
                    if (++spin > 64) __nanosleep(32);                        \
            }                                                                \
            my_gen++;                                                        \
        }                                                                    \
        __syncthreads();                                                     \
    } while (0)

__device__ __forceinline__ float warp_max_f(float v) {
#pragma unroll
    for (int o = 16; o > 0; o >>= 1) v = fmaxf(v, __shfl_down_sync(0xffffffffu, v, o));
    return v;
}
__device__ __forceinline__ float warp_sum_f(float v) {
#pragma unroll
    for (int o = 16; o > 0; o >>= 1) v += __shfl_down_sync(0xffffffffu, v, o);
    return v;
}

__global__ void __launch_bounds__(NT, 3) k_fused(
    const int* __restrict__ cls, const float* __restrict__ norm,
    const int* __restrict__ src, const int* __restrict__ dst,
    const float* __restrict__ W0, const float* __restrict__ W1,
    const float* __restrict__ W2,
    const float* __restrict__ a1_w, const float* __restrict__ a1_b,
    const float* __restrict__ a2_w, const float* __restrict__ a2_b,
    const float* __restrict__ c1_w, const float* __restrict__ c1_b,
    const float* __restrict__ c2_w, const float* __restrict__ c2_b,
    float* __restrict__ out, int out_size)
{
    const int tx   = threadIdx.x;
    const int bid  = blockIdx.x;

    // this block's contiguous quad slice
    const int q0     = bid * QPB;
    const int nq_blk = (NQ - q0 < QPB) ? (NQ - q0) : QPB;   // may be <= 0
    const bool own   = (tx < nq_blk);
    const int qi     = q0 + tx;                              // this thread's quad

    unsigned my_gen = 0;
    if (tx == 0) my_gen = ld_acquire_gpu(&g_bar_gen);

    // dst-slice cache (phases 1-3) unioned with phase-5 staging (disjoint in time)
    __shared__ union {
        int4 dst4[QPB + 1];
        struct { int dsl[ESTG]; int ssl[ESTG]; } e2;
    } shu;
    __shared__ int   sh_e1[CAPE1];
    __shared__ float sh_h[H_DIM];
    __shared__ float sh_p[NT];
    __shared__ float s_hid[LIN_DIM];
    __shared__ float s_mx, s_sum;

    // ---------- phase 1: load slice -> SMEM; dst == 0 -> S1 / E1 ----------
    if (own) {
        const int4 d4 = reinterpret_cast<const int4*>(dst)[qi];
        shu.dst4[tx] = d4;
        int dv[4] = {d4.x, d4.y, d4.z, d4.w};
#pragma unroll
        for (int k = 0; k < 4; k++) {
            if (dv[k] == 0) {
                int s = src[4 * qi + k];
                int p = atomicAdd(&g_ne1, 1);
                if (p < CAPE1) g_e1_src[p] = s;
                if (atomicCAS(&g_slot1[s], 0, -1) == 0) {
                    int sl = atomicAdd(&g_n1, 1);
                    if (sl < CAP1) g_s1_nodes[sl] = s;
                    g_slot1[s] = sl + 1;
                    atomicOr(&g_bm1[s >> 5], 1u << (s & 31));
                }
            }
        }
    }
    GRID_SYNC();

    // ---------- phase 2: dst in S1 (SMEM re-scan) -> S2 / E2 ----------
    if (own) {
        const int4 d4 = shu.dst4[tx];
        int dv[4] = {d4.x, d4.y, d4.z, d4.w};
#pragma unroll
        for (int k = 0; k < 4; k++) {
            int d = dv[k];
            if (g_bm1[d >> 5] & (1u << (d & 31))) {
                int sl = g_slot1[d] - 1;
                if (sl >= 0 && sl < CAP1) {
                    int s = src[4 * qi + k];
                    int p = atomicAdd(&g_ne2, 1);
                    if (p < CAPE2) { g_e2_src[p] = s; g_e2_dslot[p] = sl; }
                    if (atomicCAS(&g_slot2[s], 0, -1) == 0) {
                        int q = atomicAdd(&g_n2, 1);
                        if (q < CAP2) g_s2_nodes[q] = s;
                        g_slot2[s] = q + 1;
                        atomicOr(&g_bm2[s >> 5], 1u << (s & 31));
                    }
                }
            }
        }
    }
    GRID_SYNC();

    // ---------- phase 3: dst in S2 (SMEM re-scan) -> S[slot][cls[src]] += norm[src] ----------
    if (own) {
        const int4 d4 = shu.dst4[tx];
        int dv[4] = {d4.x, d4.y, d4.z, d4.w};
#pragma unroll
        for (int k = 0; k < 4; k++) {
            int d = dv[k];
            if (g_bm2[d >> 5] & (1u << (d & 31))) {
                int sl = g_slot2[d] - 1;
                if (sl >= 0 && sl < CAP2) {
                    int s = src[4 * qi + k];
                    atomicAdd(&g_S[sl * NUM_RELS + cls[s]], norm[s]);
                }
            }
        }
    }
    GRID_SYNC();

    // ---------- phase 4: msg1 for S2 nodes ----------
    // h1 = relu(S[sl] . T0) where T0[r][j] = W0[r][r][j]; msg1 = (h1 @ W1[c]) * nm
    {
        int n2v = *(volatile int*)&g_n2; if (n2v > CAP2) n2v = CAP2;
        const int j = tx & 127, q = tx >> 7;
        for (int sl = bid; sl < n2v; sl += NB) {
            if (tx < H_DIM) {
                const float* Sv = &g_S[sl * NUM_RELS];
                float h = 0.f;
#pragma unroll
                for (int r = 0; r < NUM_RELS; r++)
                    h = fmaf(Sv[r], W0[(r * NUM_RELS + r) * H_DIM + tx], h);
                sh_h[tx] = fmaxf(h, 0.f);
            }
            __syncthreads();
            int node = g_s2_nodes[sl];
            int c = cls[node];
            float nm = norm[node];
            const float* Wc = W1 + c * H_DIM * H_DIM;
            float p = 0.f;
#pragma unroll
            for (int kk = 0; kk < 32; kk++) {
                int k = q * 32 + kk;
                p = fmaf(sh_h[k], Wc[k * H_DIM + j], p);
            }
            sh_p[tx] = p;
            __syncthreads();
            if (tx < H_DIM)
                g_msg1[sl * H_DIM + tx] =
                    (sh_p[tx] + sh_p[tx + 128] + sh_p[tx + 256] + sh_p[tx + 384]) * nm;
            __syncthreads();
        }
    }
    GRID_SYNC();

    // ---------- phase 5: msg2 for S1 nodes + root accumulation ----------
    {
        int n1v = *(volatile int*)&g_n1;  if (n1v > CAP1)  n1v = CAP1;
        int ne2 = *(volatile int*)&g_ne2; if (ne2 > CAPE2) ne2 = CAPE2;
        int ne1 = *(volatile int*)&g_ne1; if (ne1 > CAPE1) ne1 = CAPE1;
        if (bid < n1v) {
            int nst = ne2 < ESTG ? ne2 : ESTG;
            for (int e = tx; e < nst; e += NT) {
                shu.e2.dsl[e] = g_e2_dslot[e];
                shu.e2.ssl[e] = g_slot2[g_e2_src[e]] - 1;
            }
            for (int i = tx; i < ne1; i += NT) sh_e1[i] = g_e1_src[i];
            __syncthreads();
            const int j = tx & 127, q = tx >> 7;
            for (int sl = bid; sl < n1v; sl += NB) {
                if (tx < H_DIM) {
                    float acc = 0.f;
                    for (int e = 0; e < nst; e++) {
                        if (shu.e2.dsl[e] == sl) {
                            int ssl = shu.e2.ssl[e];
                            if (ssl >= 0 && ssl < CAP2) acc += g_msg1[ssl * H_DIM + tx];
                        }
                    }
                    for (int e = nst; e < ne2; e++) {   // overflow fallback
                        if (g_e2_dslot[e] == sl) {
                            int ssl = g_slot2[g_e2_src[e]] - 1;
                            if (ssl >= 0 && ssl < CAP2) acc += g_msg1[ssl * H_DIM + tx];
                        }
                    }
                    sh_h[tx] = fmaxf(acc, 0.f);
                }
                __syncthreads();
                int node = g_s1_nodes[sl];
                int c = cls[node];
                float nm = norm[node];
                const float* Wc = W2 + c * H_DIM * H_DIM;
                float p = 0.f;
#pragma unroll
                for (int kk = 0; kk < 32; kk++) {
                    int k = q * 32 + kk;
                    p = fmaf(sh_h[k], Wc[k * H_DIM + j], p);
                }
                sh_p[tx] = p;
                __syncthreads();
                if (tx < H_DIM) {
                    float a = (sh_p[tx] + sh_p[tx + 128] + sh_p[tx + 256] + sh_p[tx + 384]) * nm;
                    int mult = 0;
                    for (int i = 0; i < ne1; i++) mult += (sh_e1[i] == node);
                    if (mult > 0) atomicAdd(&g_root[tx], a * (float)mult);
                }
                __syncthreads();
            }
        }
    }

    // ---------- last barrier: arrive (release); only blocks 0..2 wait ----------
    __syncthreads();
    if (tx == 0) {
        if (atom_add_release_gpu(&g_bar_cnt, 1u) == (unsigned)(NB - 1)) {
            *(volatile unsigned*)&g_bar_cnt = 0u;
            st_release_gpu(&g_bar_gen, my_gen + 1u);
        } else if (bid < 3) {
            int spin = 0;
            while (ld_acquire_gpu(&g_bar_gen) == my_gen)
                if (++spin > 64) __nanosleep(32);
        }
        my_gen++;
    }
    __syncthreads();
    if (bid >= 3) return;

    // ---------- epilogue: block1/2 clean state, block0 does heads ----------
    if (bid == 1) {
        int n1v = g_n1; if (n1v > CAP1) n1v = CAP1;
        for (int i = tx; i < n1v; i += NT) {
            int s = g_s1_nodes[i];
            g_slot1[s] = 0;
            g_bm1[s >> 5] = 0u;
        }
        __syncthreads();
        if (tx == 0) { g_n1 = 0; g_ne1 = 0; }
        return;
    }
    if (bid == 2) {
        int n2v = g_n2; if (n2v > CAP2) n2v = CAP2;
        for (int i = tx; i < n2v * NUM_RELS; i += NT) g_S[i] = 0.f;
        for (int i = tx; i < n2v; i += NT) {
            int s = g_s2_nodes[i];
            g_slot2[s] = 0;
            g_bm2[s >> 5] = 0u;
        }
        __syncthreads();
        if (tx == 0) { g_n2 = 0; g_ne2 = 0; }
        return;
    }

    // block 0: softmax(root) + actor/critic heads; then zero root
    {
        const int t = tx;
        const int lane = t & 31;
        const int wid  = t >> 5;
        if (t < H_DIM) sh_h[t] = g_root[t];
        __syncthreads();
        if (t < H_DIM) g_root[t] = 0.f;     // self-clean

        if (wid == 0) {
            float m = fmaxf(fmaxf(sh_h[lane], sh_h[lane + 32]),
                            fmaxf(sh_h[lane + 64], sh_h[lane + 96]));
            m = warp_max_f(m);
            if (lane == 0) s_mx = m;
        }
        __syncthreads();
        if (t < H_DIM) sh_h[t] = expf(sh_h[t] - s_mx);
        __syncthreads();
        if (wid == 0) {
            float sm = sh_h[lane] + sh_h[lane + 32] + sh_h[lane + 64] + sh_h[lane + 96];
            sm = warp_sum_f(sm);
            if (lane == 0) s_sum = sm;
        }
        __syncthreads();
        if (t < H_DIM) sh_h[t] *= (1.f / s_sum);    // root feats
        __syncthreads();

        // actor1: 128 -> 512 relu
        {
            float a = a1_b[t];
#pragma unroll 8
            for (int k = 0; k < H_DIM; k++) a = fmaf(sh_h[k], a1_w[k * LIN_DIM + t], a);
            s_hid[t] = fmaxf(a, 0.f);
        }
        __syncthreads();
        // actor2: 512 -> 128, 4-way k split
        {
            int q = t >> 7, j = t & 127;
            const int k0 = q * 128;
            float p = 0.f;
#pragma unroll 8
            for (int k = 0; k < 128; k++)
                p = fmaf(s_hid[k0 + k], a2_w[(k0 + k) * H_DIM + j], p);
            sh_p[t] = p;
        }
        __syncthreads();
        if (t < H_DIM)
            out[t] = a2_b[t] + sh_p[t] + sh_p[t + 128] + sh_p[t + 256] + sh_p[t + 384];
        __syncthreads();

        // critic: 128 -> 512 relu -> 1
        {
            float a = c1_b[t];
#pragma unroll 8
            for (int k = 0; k < H_DIM; k++) a = fmaf(sh_h[k], c1_w[k * LIN_DIM + t], a);
            s_hid[t] = fmaxf(a, 0.f);
        }
        __syncthreads();
        {
            float p = warp_sum_f(s_hid[t] * c2_w[t]);
            if (lane == 0) sh_p[wid] = p;
        }
        __syncthreads();
        if (t == 0) {
            float a = c2_b[0];
#pragma unroll
            for (int i = 0; i < 16; i++) a += sh_p[i];
            if (out_size > H_DIM) out[H_DIM] = a;
        }
    }
}

// ---------------- launch ----------------
extern "C" void kernel_launch(void* const* d_in, const int* in_sizes, int n_in,
                              void* d_out, int out_size) {
    const int*   cls  = (const int*)  d_in[0];
    const float* norm = (const float*)d_in[1];
    const int*   src  = (const int*)  d_in[2];
    const int*   dst  = (const int*)  d_in[3];
    const float* W0   = (const float*)d_in[4];
    const float* W1   = (const float*)d_in[5];
    const float* W2   = (const float*)d_in[6];
    const float* a1_w = (const float*)d_in[7];
    const float* a1_b = (const float*)d_in[8];
    const float* a2_w = (const float*)d_in[9];
    const float* a2_b = (const float*)d_in[10];
    const float* c1_w = (const float*)d_in[11];
    const float* c1_b = (const float*)d_in[12];
    const float* c2_w = (const float*)d_in[13];
    const float* c2_b = (const float*)d_in[14];
    float* out = (float*)d_out;

    k_fused<<<NB, NT>>>(cls, norm, src, dst, W0, W1, W2,
                        a1_w, a1_b, a2_w, a2_b, c1_w, c1_b, c2_w, c2_b,
                        out, out_size);
}